// round 1
// baseline (speedup 1.0000x reference)
#include <cuda_runtime.h>

// AlignBlock: Q/K 1x1 channel-mix -> banded cross-correlation over causal
// window (DMAX=32) -> (5,3) conv over (T,dmax) reducing H->1 -> softmax over
// dmax -> weighted causal window sum of x_ref.
//
// Shapes: B=2, C=H=64, T=512, F=64, DMAX=32. All fp32.

#define Bn 2
#define Cn 64
#define Hn 64
#define Tn 512
#define Fn 64
#define Dn 32

// Scratch (static device arrays: allocation-free rule)
__device__ float g_Q[Bn * Hn * Tn * Fn];   // 16 MB
__device__ float g_K[Bn * Hn * Tn * Fn];   // 16 MB
__device__ float g_V[Bn * Hn * Tn * Dn];   //  8 MB
__device__ float g_A[Bn * Tn * Dn];        // 128 KB

// ---------------------------------------------------------------------------
// Kernel 1: channel mix.  out[b,h,t,f] = sum_c w[h,c] * x[b,c,t,f] + bias[h]
// grid = B*T blocks, 256 threads. Each block: one (b,t), full 64h x 64f tile.
// which==0 -> g_Q, which==1 -> g_K.
// ---------------------------------------------------------------------------
__global__ void __launch_bounds__(256) k_chanmix(const float* __restrict__ x,
                                                 const float* __restrict__ w,
                                                 const float* __restrict__ bias,
                                                 int which) {
    const int tid = threadIdx.x;
    const int b = blockIdx.x >> 9;      // T = 512
    const int t = blockIdx.x & 511;

    __shared__ float xs[64][68];        // [c][f], 272B rows (16B aligned)
    __shared__ float wst[64][68];       // [c][h] (transposed weights)

#pragma unroll
    for (int it = 0; it < 16; it++) {
        int idx = tid + it * 256;
        int r = idx >> 6, q = idx & 63;           // r,h index ; q,f/c index
        xs[r][q] = x[((b * 64 + r) * 512 + t) * 64 + q];  // r=c, q=f
        wst[q][r] = w[idx];                                // idx=h*64+c -> wst[c][h]
    }
    __syncthreads();

    const int f0 = (tid & 15) * 4;
    const int h0 = (tid >> 4) * 4;

    float4 acc[4];
#pragma unroll
    for (int a = 0; a < 4; a++) acc[a] = make_float4(0.f, 0.f, 0.f, 0.f);

#pragma unroll 8
    for (int c = 0; c < 64; c++) {
        float4 xv = *(const float4*)&xs[c][f0];
        float4 wv = *(const float4*)&wst[c][h0];
        acc[0].x += wv.x * xv.x; acc[0].y += wv.x * xv.y;
        acc[0].z += wv.x * xv.z; acc[0].w += wv.x * xv.w;
        acc[1].x += wv.y * xv.x; acc[1].y += wv.y * xv.y;
        acc[1].z += wv.y * xv.z; acc[1].w += wv.y * xv.w;
        acc[2].x += wv.z * xv.x; acc[2].y += wv.z * xv.y;
        acc[2].z += wv.z * xv.z; acc[2].w += wv.z * xv.w;
        acc[3].x += wv.w * xv.x; acc[3].y += wv.w * xv.y;
        acc[3].z += wv.w * xv.z; acc[3].w += wv.w * xv.w;
    }

    float* out = which ? g_K : g_Q;
#pragma unroll
    for (int a = 0; a < 4; a++) {
        float bb = __ldg(&bias[h0 + a]);
        float4 r = acc[a];
        r.x += bb; r.y += bb; r.z += bb; r.w += bb;
        *(float4*)&out[((b * 64 + h0 + a) * 512 + t) * 64 + f0] = r;
    }
}

// ---------------------------------------------------------------------------
// Kernel 2: banded correlation.
// V[b,h,t,d] = (1/8) * sum_f Q[b,h,t,f] * K[b,h,t-31+d,f]   (0 if t-31+d < 0)
// grid = B*H*(T/64) blocks, 128 threads. t-tile = 64.
// smem is f-major so the 7-row K band is contiguous -> 2x LDS.128.
// ---------------------------------------------------------------------------
__global__ void __launch_bounds__(128) k_corr() {
    const int tid = threadIdx.x;
    const int t0 = (blockIdx.x & 7) * 64;
    const int h  = (blockIdx.x >> 3) & 63;
    const int b  = blockIdx.x >> 9;

    __shared__ float Qs[64][68];    // [f][i], i = t - t0
    __shared__ float Ks[64][100];   // [f][r], r = (t_global) - (t0 - 31), 0..94

    const float* qg = g_Q + ((b * 64 + h) * 512 + t0) * 64;
    const float* kg = g_K + ((b * 64 + h) * 512) * 64;

    for (int idx = tid; idx < 64 * 64; idx += 128) {
        int i = idx >> 6, f = idx & 63;
        Qs[f][i] = qg[i * 64 + f];
    }
    for (int idx = tid; idx < 95 * 64; idx += 128) {
        int r = idx >> 6, f = idx & 63;
        int tr = t0 - 31 + r;
        Ks[f][r] = (tr >= 0) ? kg[tr * 64 + f] : 0.0f;
    }
    __syncthreads();

    const int d0 = (tid & 7) * 4;    // 0..28
    const int i0 = (tid >> 3) * 4;   // 0..60

    float acc[4][4];
#pragma unroll
    for (int a = 0; a < 4; a++)
#pragma unroll
        for (int e = 0; e < 4; e++) acc[a][e] = 0.f;

#pragma unroll 8
    for (int f = 0; f < 64; f++) {
        float4 q4 = *(const float4*)&Qs[f][i0];
        float4 k0 = *(const float4*)&Ks[f][i0 + d0];       // rows r0..r0+3
        float4 k1 = *(const float4*)&Ks[f][i0 + d0 + 4];   // rows r0+4..r0+7
        float qq[4] = {q4.x, q4.y, q4.z, q4.w};
        float kk[8] = {k0.x, k0.y, k0.z, k0.w, k1.x, k1.y, k1.z, k1.w};
#pragma unroll
        for (int a = 0; a < 4; a++)
#pragma unroll
            for (int e = 0; e < 4; e++)
                acc[a][e] += qq[a] * kk[a + e];   // row = i0+a + d0+e - (i0+d0)
    }

    float* vg = g_V + ((b * 64 + h) * 512 + t0) * 32;
#pragma unroll
    for (int a = 0; a < 4; a++) {
        float4 r = make_float4(acc[a][0] * 0.125f, acc[a][1] * 0.125f,
                               acc[a][2] * 0.125f, acc[a][3] * 0.125f);
        *(float4*)&vg[(i0 + a) * 32 + d0] = r;
    }
}

// ---------------------------------------------------------------------------
// Kernel 3: (5,3) conv over (T,dmax), H->1, + bias, + softmax over dmax.
// Vc[b,t,d] = sum_h sum_{i=0..4,j=0..2} V[b,h,t-4+i,d-1+j] * w[h,i,j] + bconv
// A[b,t,:] = softmax(Vc[b,t,:]).  grid = B*T blocks, 256 threads.
// ---------------------------------------------------------------------------
__global__ void __launch_bounds__(256) k_convsoftmax(const float* __restrict__ wconv,
                                                     const float* __restrict__ bconv) {
    const int tid = threadIdx.x;
    const int b = blockIdx.x >> 9;
    const int t = blockIdx.x & 511;

    __shared__ float wcs[960];      // [h][i][j]
    __shared__ float red[8][33];

    for (int idx = tid; idx < 960; idx += 256) wcs[idx] = wconv[idx];
    __syncthreads();

    const int d = tid & 31;
    const int hg = tid >> 5;        // 0..7

    float acc = 0.f;
#pragma unroll
    for (int m = 0; m < 8; m++) {
        int h = hg * 8 + m;
        const float* vb = g_V + ((b * 64 + h) * 512) * 32;
        const float* wr = wcs + h * 15;
#pragma unroll
        for (int i = 0; i < 5; i++) {
            int tt = t - 4 + i;
            if (tt < 0) continue;
#pragma unroll
            for (int j = 0; j < 3; j++) {
                int dd = d - 1 + j;
                if (dd < 0 || dd >= 32) continue;
                acc += vb[tt * 32 + dd] * wr[i * 3 + j];
            }
        }
    }
    red[hg][d] = acc;
    __syncthreads();

    if (tid < 32) {
        float v = __ldg(&bconv[0]);
#pragma unroll
        for (int g = 0; g < 8; g++) v += red[g][tid];
        float mx = v;
#pragma unroll
        for (int o = 16; o > 0; o >>= 1)
            mx = fmaxf(mx, __shfl_xor_sync(0xffffffffu, mx, o));
        float e = __expf(v - mx);
        float s = e;
#pragma unroll
        for (int o = 16; o > 0; o >>= 1)
            s += __shfl_xor_sync(0xffffffffu, s, o);
        g_A[(b * 512 + t) * 32 + tid] = e / s;
    }
}

// ---------------------------------------------------------------------------
// Kernel 4: aligned[b,c,t,f] = sum_d A[b,t,d] * x_ref[b,c,t-31+d,f]
// grid = B*C*(T/64) blocks, 256 threads. t-tile = 64.
// ---------------------------------------------------------------------------
__global__ void __launch_bounds__(256) k_align(const float* __restrict__ xref,
                                               float* __restrict__ out) {
    const int tid = threadIdx.x;
    const int t0 = (blockIdx.x & 7) * 64;
    const int c  = (blockIdx.x >> 3) & 63;
    const int b  = blockIdx.x >> 9;

    __shared__ float As[64][36];    // [i][d], 144B rows (16B aligned)
    __shared__ float Xs[95][68];    // [r][f], r = t_global - (t0 - 31)

    const float* ag = g_A + (b * 512 + t0) * 32;
    const float* xg = xref + ((b * 64 + c) * 512) * 64;

    for (int idx = tid; idx < 64 * 32; idx += 256) {
        int i = idx >> 5, d = idx & 31;
        As[i][d] = ag[i * 32 + d];
    }
    for (int idx = tid; idx < 95 * 64; idx += 256) {
        int r = idx >> 6, f = idx & 63;
        int tr = t0 - 31 + r;
        Xs[r][f] = (tr >= 0) ? xg[tr * 64 + f] : 0.0f;
    }
    __syncthreads();

    const int f0 = (tid & 15) * 4;   // 0..60
    const int i0 = (tid >> 4) * 4;   // 0..60

    float4 acc[4];
#pragma unroll
    for (int a = 0; a < 4; a++) acc[a] = make_float4(0.f, 0.f, 0.f, 0.f);

#pragma unroll 2
    for (int d0 = 0; d0 < 32; d0 += 4) {
        float4 av[4];
#pragma unroll
        for (int a = 0; a < 4; a++) av[a] = *(const float4*)&As[i0 + a][d0];
        float4 xv[7];
#pragma unroll
        for (int k = 0; k < 7; k++)
            xv[k] = *(const float4*)&Xs[i0 + d0 + k][f0];   // row = i0+d0+k <= 94
#pragma unroll
        for (int a = 0; a < 4; a++) {
            float aa[4] = {av[a].x, av[a].y, av[a].z, av[a].w};
#pragma unroll
            for (int dd = 0; dd < 4; dd++) {
                float4 x4 = xv[a + dd];   // (i0+a) + (d0+dd) - (i0+d0) = a+dd
                acc[a].x += aa[dd] * x4.x;
                acc[a].y += aa[dd] * x4.y;
                acc[a].z += aa[dd] * x4.z;
                acc[a].w += aa[dd] * x4.w;
            }
        }
    }

    float* og = out + ((b * 64 + c) * 512 + t0) * 64;
#pragma unroll
    for (int a = 0; a < 4; a++)
        *(float4*)&og[(i0 + a) * 64 + f0] = acc[a];
}

// ---------------------------------------------------------------------------
extern "C" void kernel_launch(void* const* d_in, const int* in_sizes, int n_in,
                              void* d_out, int out_size) {
    (void)in_sizes; (void)n_in; (void)out_size;
    const float* x_mic  = (const float*)d_in[0];
    const float* x_ref  = (const float*)d_in[1];
    const float* w_mic  = (const float*)d_in[2];
    const float* b_mic  = (const float*)d_in[3];
    const float* w_ref  = (const float*)d_in[4];
    const float* b_ref  = (const float*)d_in[5];
    const float* w_conv = (const float*)d_in[6];
    const float* b_conv = (const float*)d_in[7];
    float* out = (float*)d_out;

    k_chanmix<<<Bn * Tn, 256>>>(x_mic, w_mic, b_mic, 0);           // -> g_Q
    k_chanmix<<<Bn * Tn, 256>>>(x_ref, w_ref, b_ref, 1);           // -> g_K
    k_corr<<<Bn * Hn * (Tn / 64), 128>>>();                        // -> g_V
    k_convsoftmax<<<Bn * Tn, 256>>>(w_conv, b_conv);               // -> g_A
    k_align<<<Bn * Cn * (Tn / 64), 256>>>(x_ref, out);             // -> out
}